// round 2
// baseline (speedup 1.0000x reference)
#include <cuda_runtime.h>
#include <math.h>

// Problem constants
#define NB     4
#define TSEQ   2048
#define DMODEL 1024
#define DFF    4096
#define NTOK   (NB * TSEQ)   // 8192

// ---------------------------------------------------------------------------
// Scratch (device globals — no allocations allowed)
// ---------------------------------------------------------------------------
__device__ float g_Q [NTOK * DMODEL];                     // Q, later reused as attn-out (A@V)
__device__ float g_Km[NTOK * DMODEL];                     // K, later reused as O-proj
__device__ float g_Vm[NTOK * DMODEL];                     // V, later reused as H2 (FFN out)
__device__ float g_S [(size_t)NB * TSEQ * TSEQ];          // attention scores / probs
__device__ float g_H1[NTOK * DMODEL];                     // first LN output (needed twice)
__device__ float g_FF[(size_t)NTOK * DFF];                // GELU(H1@W1+b1)

// ---------------------------------------------------------------------------
// SGEMM: C = alpha * A @ B(^T) [+ bias] [gelu], 128x128x16 tiles, 256 threads
//   EPI: 0 = none, 1 = +bias, 2 = +bias then exact GELU
//   TB : B operand is [N,K] row-major (compute A @ B^T)
//   CSKIP: skip tiles strictly above the diagonal (causal scores)
//   CK : clamp K loop to (by+1)*BM (causal A@V — probs are zero beyond t)
// All dims are multiples of tile sizes; no bounds checks.
// ---------------------------------------------------------------------------
template <int EPI, bool TB, bool CSKIP, bool CK>
__global__ __launch_bounds__(256)
void sgemm_kernel(const float* __restrict__ A, const float* __restrict__ B,
                  const float* __restrict__ bias, float* __restrict__ C,
                  int M, int N, int K, float alpha,
                  long long sA, long long sB, long long sC)
{
    constexpr int BM = 128, BN = 128, BK = 16;
    const int bx = blockIdx.x, by = blockIdx.y, bz = blockIdx.z;
    if (CSKIP && bx > by) return;             // fully-masked score tile

    A += (long long)bz * sA;
    B += (long long)bz * sB;
    C += (long long)bz * sC;

    const int m0 = by * BM, n0 = bx * BN;
    const int kEnd = CK ? min(K, (by + 1) * BM) : K;

    __shared__ float As[BK][BM];
    __shared__ float Bs[BK][BN];

    const int tid = threadIdx.x;
    const int tx = tid & 15;       // 0..15 -> N
    const int ty = tid >> 4;       // 0..15 -> M

    float acc[8][8] = {};
    float a_reg[8], b_reg[8];

    for (int k0 = 0; k0 < kEnd; k0 += BK) {
        // ---- load A tile [BM x BK], store transposed As[k][m] ----
        #pragma unroll
        for (int i = 0; i < 2; i++) {
            int f = tid + i * 256;               // 512 float4 loads
            int r = f >> 2, c4 = f & 3;
            float4 v = *(const float4*)(A + (long long)(m0 + r) * K + k0 + c4 * 4);
            As[c4 * 4 + 0][r] = v.x;
            As[c4 * 4 + 1][r] = v.y;
            As[c4 * 4 + 2][r] = v.z;
            As[c4 * 4 + 3][r] = v.w;
        }
        // ---- load B tile ----
        if (!TB) {   // B is [K,N]
            #pragma unroll
            for (int i = 0; i < 2; i++) {
                int f = tid + i * 256;
                int r = f >> 5, c4 = f & 31;
                float4 v = *(const float4*)(B + (long long)(k0 + r) * N + n0 + c4 * 4);
                *(float4*)&Bs[r][c4 * 4] = v;
            }
        } else {     // B is [N,K], load transposed
            #pragma unroll
            for (int i = 0; i < 2; i++) {
                int f = tid + i * 256;
                int r = f >> 2, c4 = f & 3;
                float4 v = *(const float4*)(B + (long long)(n0 + r) * K + k0 + c4 * 4);
                Bs[c4 * 4 + 0][r] = v.x;
                Bs[c4 * 4 + 1][r] = v.y;
                Bs[c4 * 4 + 2][r] = v.z;
                Bs[c4 * 4 + 3][r] = v.w;
            }
        }
        __syncthreads();

        #pragma unroll
        for (int k = 0; k < BK; k++) {
            *(float4*)&a_reg[0] = *(const float4*)&As[k][ty * 8];
            *(float4*)&a_reg[4] = *(const float4*)&As[k][ty * 8 + 4];
            *(float4*)&b_reg[0] = *(const float4*)&Bs[k][tx * 8];
            *(float4*)&b_reg[4] = *(const float4*)&Bs[k][tx * 8 + 4];
            #pragma unroll
            for (int i = 0; i < 8; i++)
                #pragma unroll
                for (int j = 0; j < 8; j++)
                    acc[i][j] = fmaf(a_reg[i], b_reg[j], acc[i][j]);
        }
        __syncthreads();
    }

    // ---- epilogue ----
    #pragma unroll
    for (int i = 0; i < 8; i++) {
        const int m = m0 + ty * 8 + i;
        #pragma unroll
        for (int j = 0; j < 8; j++) {
            float v = acc[i][j] * alpha;
            if (EPI >= 1) v += bias[n0 + tx * 8 + j];
            if (EPI == 2) v = 0.5f * v * (1.0f + erff(v * 0.70710678118654752f));
            acc[i][j] = v;
        }
        float* cp = C + (long long)m * N + n0 + tx * 8;
        *(float4*)cp       = *(float4*)&acc[i][0];
        *(float4*)(cp + 4) = *(float4*)&acc[i][4];
    }
}

// ---------------------------------------------------------------------------
// Causal softmax over one row t of S[b]: softmax(row[0..t]), zero row[t+1..T)
// ---------------------------------------------------------------------------
__global__ __launch_bounds__(256)
void softmax_causal_kernel(float* __restrict__ S)
{
    const int t = blockIdx.x, b = blockIdx.y;
    float* row = S + ((long long)b * TSEQ + t) * TSEQ;
    const int len = t + 1;
    const int tid = threadIdx.x;
    __shared__ float red[256];

    float m = -1e30f;
    for (int s = tid; s < len; s += 256) m = fmaxf(m, row[s]);
    red[tid] = m; __syncthreads();
    for (int o = 128; o > 0; o >>= 1) {
        if (tid < o) red[tid] = fmaxf(red[tid], red[tid + o]);
        __syncthreads();
    }
    m = red[0];
    __syncthreads();

    float sum = 0.0f;
    for (int s = tid; s < len; s += 256) {
        float e = expf(row[s] - m);
        row[s] = e;
        sum += e;
    }
    red[tid] = sum; __syncthreads();
    for (int o = 128; o > 0; o >>= 1) {
        if (tid < o) red[tid] += red[tid + o];
        __syncthreads();
    }
    const float inv = 1.0f / red[0];

    for (int s = tid; s < len; s += 256)       row[s] *= inv;
    for (int s = len + tid; s < TSEQ; s += 256) row[s] = 0.0f;   // zero tail for A@V
}

// ---------------------------------------------------------------------------
// out = LayerNorm(Xa + Xb) * g + be   (one block per row, D = 1024)
// ---------------------------------------------------------------------------
__global__ __launch_bounds__(256)
void add_ln_kernel(const float* __restrict__ Xa, const float* __restrict__ Xb,
                   const float* __restrict__ g,  const float* __restrict__ be,
                   float* __restrict__ out)
{
    const int row = blockIdx.x;
    const int tid = threadIdx.x;
    const float* pa = Xa + (long long)row * DMODEL;
    const float* pb = Xb + (long long)row * DMODEL;

    float x[4];
    float s1 = 0.0f, s2 = 0.0f;
    #pragma unroll
    for (int i = 0; i < 4; i++) {
        int c = tid + i * 256;
        x[i] = pa[c] + pb[c];
        s1 += x[i];
        s2 += x[i] * x[i];
    }
    __shared__ float r1[256], r2[256];
    r1[tid] = s1; r2[tid] = s2; __syncthreads();
    for (int o = 128; o > 0; o >>= 1) {
        if (tid < o) { r1[tid] += r1[tid + o]; r2[tid] += r2[tid + o]; }
        __syncthreads();
    }
    const float mu  = r1[0] * (1.0f / DMODEL);
    const float var = r2[0] * (1.0f / DMODEL) - mu * mu;
    const float inv = rsqrtf(var + 1e-5f);

    float* po = out + (long long)row * DMODEL;
    #pragma unroll
    for (int i = 0; i < 4; i++) {
        int c = tid + i * 256;
        po[c] = (x[i] - mu) * inv * g[c] + be[c];
    }
}

// ---------------------------------------------------------------------------
// Host launch
// ---------------------------------------------------------------------------
extern "C" void kernel_launch(void* const* d_in, const int* in_sizes, int n_in,
                              void* d_out, int out_size)
{
    (void)in_sizes; (void)n_in; (void)out_size;
    const float* X   = (const float*)d_in[0];
    const float* WQ  = (const float*)d_in[1];
    const float* bQ  = (const float*)d_in[2];
    const float* WK  = (const float*)d_in[3];
    const float* bK  = (const float*)d_in[4];
    const float* WV  = (const float*)d_in[5];
    const float* bV  = (const float*)d_in[6];
    const float* WO  = (const float*)d_in[7];
    const float* bO  = (const float*)d_in[8];
    const float* W1  = (const float*)d_in[9];
    const float* b1  = (const float*)d_in[10];
    const float* W2  = (const float*)d_in[11];
    const float* b2  = (const float*)d_in[12];
    const float* g1  = (const float*)d_in[13];
    const float* be1 = (const float*)d_in[14];
    const float* g2  = (const float*)d_in[15];
    const float* be2 = (const float*)d_in[16];
    float* out = (float*)d_out;

    float *Q, *Km, *Vm, *S, *H1, *FF;
    cudaGetSymbolAddress((void**)&Q,  g_Q);
    cudaGetSymbolAddress((void**)&Km, g_Km);
    cudaGetSymbolAddress((void**)&Vm, g_Vm);
    cudaGetSymbolAddress((void**)&S,  g_S);
    cudaGetSymbolAddress((void**)&H1, g_H1);
    cudaGetSymbolAddress((void**)&FF, g_FF);

    const dim3 blk(256);
    const dim3 gProj(DMODEL / 128, NTOK / 128);            // 8 x 64
    const dim3 gS(TSEQ / 128, TSEQ / 128, NB);             // 16 x 16 x 4
    const dim3 gAV(DMODEL / 128, TSEQ / 128, NB);          // 8 x 16 x 4
    const dim3 gFF1(DFF / 128, NTOK / 128);                // 32 x 64

    const long long sQK = (long long)TSEQ * DMODEL;
    const long long sSS = (long long)TSEQ * TSEQ;

    // Q, K, V projections (treat [B,T,D] as [8192, D])
    sgemm_kernel<1, false, false, false><<<gProj, blk>>>(X, WQ, bQ, Q,  NTOK, DMODEL, DMODEL, 1.0f, 0, 0, 0);
    sgemm_kernel<1, false, false, false><<<gProj, blk>>>(X, WK, bK, Km, NTOK, DMODEL, DMODEL, 1.0f, 0, 0, 0);
    sgemm_kernel<1, false, false, false><<<gProj, blk>>>(X, WV, bV, Vm, NTOK, DMODEL, DMODEL, 1.0f, 0, 0, 0);

    // scores = (Q @ K^T) / sqrt(D), batched, upper-triangle tiles skipped
    sgemm_kernel<0, true, true, false><<<gS, blk>>>(Q, Km, nullptr, S, TSEQ, TSEQ, DMODEL,
                                                    0.03125f, sQK, sQK, sSS);

    // causal softmax (writes zeros above the diagonal)
    softmax_causal_kernel<<<dim3(TSEQ, NB), blk>>>(S);

    // attn = probs @ V   (K-loop clamped to causal extent; result reuses g_Q)
    sgemm_kernel<0, false, false, true><<<gAV, blk>>>(S, Vm, nullptr, Q, TSEQ, DMODEL, TSEQ,
                                                      1.0f, sSS, sQK, sQK);

    // O projection (result reuses g_Km)
    sgemm_kernel<1, false, false, false><<<gProj, blk>>>(Q, WO, bO, Km, NTOK, DMODEL, DMODEL, 1.0f, 0, 0, 0);

    // H1 = LN(O + X)
    add_ln_kernel<<<NTOK, blk>>>(Km, X, g1, be1, H1);

    // FF = gelu(H1 @ W1 + b1)
    sgemm_kernel<2, false, false, false><<<gFF1, blk>>>(H1, W1, b1, FF, NTOK, DFF, DMODEL, 1.0f, 0, 0, 0);

    // H2 = FF @ W2 + b2  (result reuses g_Vm)
    sgemm_kernel<1, false, false, false><<<gProj, blk>>>(FF, W2, b2, Vm, NTOK, DMODEL, DFF, 1.0f, 0, 0, 0);

    // out = LN(H2 + H1)
    add_ln_kernel<<<NTOK, blk>>>(Vm, H1, g2, be2, out);
}

// round 3
// speedup vs baseline: 1.1607x; 1.1607x over previous
#include <cuda_runtime.h>
#include <mma.h>
#include <math.h>

using namespace nvcuda;

// Problem constants
#define NB     4
#define TSEQ   2048
#define DMODEL 1024
#define DFF    4096
#define NTOK   (NB * TSEQ)   // 8192

// ---------------------------------------------------------------------------
// Scratch (device globals — no allocations allowed)
// ---------------------------------------------------------------------------
__device__ float g_Q [NTOK * DMODEL];
__device__ float g_Km[NTOK * DMODEL];
__device__ float g_Vm[NTOK * DMODEL];
__device__ float g_S [(size_t)NB * TSEQ * TSEQ];
__device__ float g_H1[NTOK * DMODEL];
__device__ float g_FF[(size_t)NTOK * DFF];

// ---------------------------------------------------------------------------
// TF32 tensor-core GEMM: C = alpha * A @ B(^T) [+ bias] [gelu]
// Block tile 128x128, BK=32, 256 threads (8 warps, each a 64x32 warp tile).
//   EPI: 0 = none, 1 = +bias, 2 = +bias then exact GELU
//   TB : B operand is [N,K] row-major (compute A @ B^T)
//   CSKIP: skip tiles strictly above diagonal (causal scores)
//   CK : clamp K loop to (by+1)*BM (causal A@V)
// All dims are multiples of tile sizes; no bounds checks.
// ---------------------------------------------------------------------------
template <int EPI, bool TB, bool CSKIP, bool CK>
__global__ __launch_bounds__(256)
void tf32gemm_kernel(const float* __restrict__ A, const float* __restrict__ B,
                     const float* __restrict__ bias, float* __restrict__ C,
                     int M, int N, int K, float alpha,
                     long long sA, long long sB, long long sC)
{
    constexpr int BM = 128, BN = 128, BK = 32;
    constexpr int AST = BK + 8;            // A smem stride (40: mult of 8 for wmma ldm)
    constexpr int STG = 136;               // staging stride (mult of 8)

    const int bx = blockIdx.x, by = blockIdx.y, bz = blockIdx.z;
    if (CSKIP && bx > by) return;

    A += (long long)bz * sA;
    B += (long long)bz * sB;
    C += (long long)bz * sC;

    const int m0 = by * BM, n0 = bx * BN;
    const int kEnd = CK ? min(K, (by + 1) * BM) : K;

    // 40KB shared: As [128 x 40], Bs [32 x 128] or [128 x 40]; staging overlaps.
    __shared__ __align__(16) float smem[10240];
    float* As = smem;                          // 128*40 = 5120 floats
    float* Bs = smem + 5120;                   // up to 5120 floats
    float* Stage = smem;                       // 64*136 = 8704 floats (after mainloop)

    const int tid = threadIdx.x;
    const int wid = tid >> 5;
    const int wy = wid >> 2;                   // 0..1 -> M  (64 rows)
    const int wx = wid & 3;                    // 0..3 -> N  (32 cols)

    wmma::fragment<wmma::accumulator, 16, 16, 8, float> c_frag[4][2];
    #pragma unroll
    for (int i = 0; i < 4; i++)
        #pragma unroll
        for (int j = 0; j < 2; j++)
            wmma::fill_fragment(c_frag[i][j], 0.0f);

    for (int k0 = 0; k0 < kEnd; k0 += BK) {
        // ---- load A tile [128 x 32] row-major into As (stride 40) ----
        #pragma unroll
        for (int i = 0; i < 4; i++) {
            int f = tid + i * 256;             // 1024 float4 loads
            int r = f >> 3, c4 = f & 7;
            float4 v = *(const float4*)(A + (long long)(m0 + r) * K + k0 + c4 * 4);
            *(float4*)&As[r * AST + c4 * 4] = v;
        }
        // ---- load B tile ----
        if (!TB) {   // B is [K,N]: Bs [32 x 128] row-major
            #pragma unroll
            for (int i = 0; i < 4; i++) {
                int f = tid + i * 256;
                int r = f >> 5, c4 = f & 31;
                float4 v = *(const float4*)(B + (long long)(k0 + r) * N + n0 + c4 * 4);
                *(float4*)&Bs[r * BN + c4 * 4] = v;
            }
        } else {     // B is [N,K]: Bs [128 x 40] row-major (== col-major K x N)
            #pragma unroll
            for (int i = 0; i < 4; i++) {
                int f = tid + i * 256;
                int r = f >> 3, c4 = f & 7;
                float4 v = *(const float4*)(B + (long long)(n0 + r) * K + k0 + c4 * 4);
                *(float4*)&Bs[r * AST + c4 * 4] = v;
            }
        }
        __syncthreads();

        #pragma unroll
        for (int kk = 0; kk < BK; kk += 8) {
            wmma::fragment<wmma::matrix_a, 16, 16, 8, wmma::precision::tf32, wmma::row_major> a_frag[4];
            #pragma unroll
            for (int i = 0; i < 4; i++) {
                wmma::load_matrix_sync(a_frag[i], &As[(wy * 64 + i * 16) * AST + kk], AST);
                #pragma unroll
                for (int e = 0; e < a_frag[i].num_elements; e++)
                    a_frag[i].x[e] = wmma::__float_to_tf32(a_frag[i].x[e]);
            }
            if (!TB) {
                wmma::fragment<wmma::matrix_b, 16, 16, 8, wmma::precision::tf32, wmma::row_major> b_frag[2];
                #pragma unroll
                for (int j = 0; j < 2; j++) {
                    wmma::load_matrix_sync(b_frag[j], &Bs[kk * BN + wx * 32 + j * 16], BN);
                    #pragma unroll
                    for (int e = 0; e < b_frag[j].num_elements; e++)
                        b_frag[j].x[e] = wmma::__float_to_tf32(b_frag[j].x[e]);
                }
                #pragma unroll
                for (int i = 0; i < 4; i++)
                    #pragma unroll
                    for (int j = 0; j < 2; j++)
                        wmma::mma_sync(c_frag[i][j], a_frag[i], b_frag[j], c_frag[i][j]);
            } else {
                wmma::fragment<wmma::matrix_b, 16, 16, 8, wmma::precision::tf32, wmma::col_major> b_frag[2];
                #pragma unroll
                for (int j = 0; j < 2; j++) {
                    wmma::load_matrix_sync(b_frag[j], &Bs[(wx * 32 + j * 16) * AST + kk], AST);
                    #pragma unroll
                    for (int e = 0; e < b_frag[j].num_elements; e++)
                        b_frag[j].x[e] = wmma::__float_to_tf32(b_frag[j].x[e]);
                }
                #pragma unroll
                for (int i = 0; i < 4; i++)
                    #pragma unroll
                    for (int j = 0; j < 2; j++)
                        wmma::mma_sync(c_frag[i][j], a_frag[i], b_frag[j], c_frag[i][j]);
            }
        }
        __syncthreads();
    }

    // ---- epilogue: two phases through 64x128 smem staging ----
    #pragma unroll
    for (int p = 0; p < 2; p++) {
        if (wy == p) {
            #pragma unroll
            for (int i = 0; i < 4; i++)
                #pragma unroll
                for (int j = 0; j < 2; j++)
                    wmma::store_matrix_sync(&Stage[(i * 16) * STG + wx * 32 + j * 16],
                                            c_frag[i][j], STG, wmma::mem_row_major);
        }
        __syncthreads();
        #pragma unroll
        for (int i = 0; i < 8; i++) {
            int f = tid + i * 256;             // 2048 float4 stores over 64x128
            int r = f >> 5, c4 = f & 31;
            float4 v = *(const float4*)&Stage[r * STG + c4 * 4];
            float out[4] = {v.x, v.y, v.z, v.w};
            #pragma unroll
            for (int e = 0; e < 4; e++) {
                float x = out[e] * alpha;
                if (EPI >= 1) x += bias[n0 + c4 * 4 + e];
                if (EPI == 2) x = 0.5f * x * (1.0f + erff(x * 0.70710678118654752f));
                out[e] = x;
            }
            *(float4*)(C + (long long)(m0 + p * 64 + r) * N + n0 + c4 * 4) = *(const float4*)out;
        }
        __syncthreads();
    }
}

// ---------------------------------------------------------------------------
// Causal softmax over one row t of S[b]: softmax(row[0..t]), zero row[t+1..T)
// ---------------------------------------------------------------------------
__global__ __launch_bounds__(256)
void softmax_causal_kernel(float* __restrict__ S)
{
    const int t = blockIdx.x, b = blockIdx.y;
    float* row = S + ((long long)b * TSEQ + t) * TSEQ;
    const int len = t + 1;
    const int tid = threadIdx.x;
    __shared__ float red[256];

    float m = -1e30f;
    for (int s = tid; s < len; s += 256) m = fmaxf(m, row[s]);
    red[tid] = m; __syncthreads();
    for (int o = 128; o > 0; o >>= 1) {
        if (tid < o) red[tid] = fmaxf(red[tid], red[tid + o]);
        __syncthreads();
    }
    m = red[0];
    __syncthreads();

    float sum = 0.0f;
    for (int s = tid; s < len; s += 256) {
        float e = expf(row[s] - m);
        row[s] = e;
        sum += e;
    }
    red[tid] = sum; __syncthreads();
    for (int o = 128; o > 0; o >>= 1) {
        if (tid < o) red[tid] += red[tid + o];
        __syncthreads();
    }
    const float inv = 1.0f / red[0];

    for (int s = tid; s < len; s += 256)        row[s] *= inv;
    for (int s = len + tid; s < TSEQ; s += 256) row[s] = 0.0f;
}

// ---------------------------------------------------------------------------
// out = LayerNorm(Xa + Xb) * g + be   (one block per row, D = 1024)
// ---------------------------------------------------------------------------
__global__ __launch_bounds__(256)
void add_ln_kernel(const float* __restrict__ Xa, const float* __restrict__ Xb,
                   const float* __restrict__ g,  const float* __restrict__ be,
                   float* __restrict__ out)
{
    const int row = blockIdx.x;
    const int tid = threadIdx.x;
    const float* pa = Xa + (long long)row * DMODEL;
    const float* pb = Xb + (long long)row * DMODEL;

    float x[4];
    float s1 = 0.0f, s2 = 0.0f;
    #pragma unroll
    for (int i = 0; i < 4; i++) {
        int c = tid + i * 256;
        x[i] = pa[c] + pb[c];
        s1 += x[i];
        s2 += x[i] * x[i];
    }
    __shared__ float r1[256], r2[256];
    r1[tid] = s1; r2[tid] = s2; __syncthreads();
    for (int o = 128; o > 0; o >>= 1) {
        if (tid < o) { r1[tid] += r1[tid + o]; r2[tid] += r2[tid + o]; }
        __syncthreads();
    }
    const float mu  = r1[0] * (1.0f / DMODEL);
    const float var = r2[0] * (1.0f / DMODEL) - mu * mu;
    const float inv = rsqrtf(var + 1e-5f);

    float* po = out + (long long)row * DMODEL;
    #pragma unroll
    for (int i = 0; i < 4; i++) {
        int c = tid + i * 256;
        po[c] = (x[i] - mu) * inv * g[c] + be[c];
    }
}

// ---------------------------------------------------------------------------
// Host launch
// ---------------------------------------------------------------------------
extern "C" void kernel_launch(void* const* d_in, const int* in_sizes, int n_in,
                              void* d_out, int out_size)
{
    (void)in_sizes; (void)n_in; (void)out_size;
    const float* X   = (const float*)d_in[0];
    const float* WQ  = (const float*)d_in[1];
    const float* bQ  = (const float*)d_in[2];
    const float* WK  = (const float*)d_in[3];
    const float* bK  = (const float*)d_in[4];
    const float* WV  = (const float*)d_in[5];
    const float* bV  = (const float*)d_in[6];
    const float* WO  = (const float*)d_in[7];
    const float* bO  = (const float*)d_in[8];
    const float* W1  = (const float*)d_in[9];
    const float* b1  = (const float*)d_in[10];
    const float* W2  = (const float*)d_in[11];
    const float* b2  = (const float*)d_in[12];
    const float* g1  = (const float*)d_in[13];
    const float* be1 = (const float*)d_in[14];
    const float* g2  = (const float*)d_in[15];
    const float* be2 = (const float*)d_in[16];
    float* out = (float*)d_out;

    float *Q, *Km, *Vm, *S, *H1, *FF;
    cudaGetSymbolAddress((void**)&Q,  g_Q);
    cudaGetSymbolAddress((void**)&Km, g_Km);
    cudaGetSymbolAddress((void**)&Vm, g_Vm);
    cudaGetSymbolAddress((void**)&S,  g_S);
    cudaGetSymbolAddress((void**)&H1, g_H1);
    cudaGetSymbolAddress((void**)&FF, g_FF);

    const dim3 blk(256);
    const dim3 gProj(DMODEL / 128, NTOK / 128);            // 8 x 64
    const dim3 gS(TSEQ / 128, TSEQ / 128, NB);             // 16 x 16 x 4
    const dim3 gAV(DMODEL / 128, TSEQ / 128, NB);          // 8 x 16 x 4
    const dim3 gFF1(DFF / 128, NTOK / 128);                // 32 x 64

    const long long sQK = (long long)TSEQ * DMODEL;
    const long long sSS = (long long)TSEQ * TSEQ;

    // Q, K, V projections
    tf32gemm_kernel<1, false, false, false><<<gProj, blk>>>(X, WQ, bQ, Q,  NTOK, DMODEL, DMODEL, 1.0f, 0, 0, 0);
    tf32gemm_kernel<1, false, false, false><<<gProj, blk>>>(X, WK, bK, Km, NTOK, DMODEL, DMODEL, 1.0f, 0, 0, 0);
    tf32gemm_kernel<1, false, false, false><<<gProj, blk>>>(X, WV, bV, Vm, NTOK, DMODEL, DMODEL, 1.0f, 0, 0, 0);

    // scores = (Q @ K^T) / sqrt(D)
    tf32gemm_kernel<0, true, true, false><<<gS, blk>>>(Q, Km, nullptr, S, TSEQ, TSEQ, DMODEL,
                                                       0.03125f, sQK, sQK, sSS);

    // causal softmax
    softmax_causal_kernel<<<dim3(TSEQ, NB), blk>>>(S);

    // attn = probs @ V  (reuses g_Q)
    tf32gemm_kernel<0, false, false, true><<<gAV, blk>>>(S, Vm, nullptr, Q, TSEQ, DMODEL, TSEQ,
                                                         1.0f, sSS, sQK, sQK);

    // O projection (reuses g_Km)
    tf32gemm_kernel<1, false, false, false><<<gProj, blk>>>(Q, WO, bO, Km, NTOK, DMODEL, DMODEL, 1.0f, 0, 0, 0);

    // H1 = LN(O + X)
    add_ln_kernel<<<NTOK, blk>>>(Km, X, g1, be1, H1);

    // FF = gelu(H1 @ W1 + b1)
    tf32gemm_kernel<2, false, false, false><<<gFF1, blk>>>(H1, W1, b1, FF, NTOK, DFF, DMODEL, 1.0f, 0, 0, 0);

    // H2 = FF @ W2 + b2  (reuses g_Vm)
    tf32gemm_kernel<1, false, false, false><<<gProj, blk>>>(FF, W2, b2, Vm, NTOK, DMODEL, DFF, 1.0f, 0, 0, 0);

    // out = LN(H2 + H1)
    add_ln_kernel<<<NTOK, blk>>>(Vm, H1, g2, be2, out);
}

// round 4
// speedup vs baseline: 1.4556x; 1.2540x over previous
#include <cuda_runtime.h>
#include <mma.h>
#include <math.h>
#include <stdint.h>

using namespace nvcuda;

// Problem constants
#define NB     4
#define TSEQ   2048
#define DMODEL 1024
#define DFF    4096
#define NTOK   (NB * TSEQ)   // 8192

// ---------------------------------------------------------------------------
// Scratch (device globals — no allocations allowed)
// ---------------------------------------------------------------------------
__device__ float g_Q [NTOK * DMODEL];
__device__ float g_Km[NTOK * DMODEL];
__device__ float g_Vm[NTOK * DMODEL];
__device__ float g_S [(size_t)NB * TSEQ * TSEQ];
__device__ float g_H1[NTOK * DMODEL];
__device__ float g_FF[(size_t)NTOK * DFF];

// ---------------------------------------------------------------------------
// cp.async helpers
// ---------------------------------------------------------------------------
__device__ __forceinline__ uint32_t smem_u32(const void* p) {
    return (uint32_t)__cvta_generic_to_shared(p);
}
#define CP_ASYNC16(dst, src) \
    asm volatile("cp.async.cg.shared.global [%0], [%1], 16;" :: "r"(dst), "l"(src))
#define CP_COMMIT() asm volatile("cp.async.commit_group;")
#define CP_WAIT0()  asm volatile("cp.async.wait_group 0;")

// ---------------------------------------------------------------------------
// TF32 tensor-core GEMM, cp.async double-buffered.
// Block tile 128x128, BK=16, 256 threads (8 warps, each a 64x32 warp tile),
// 2 CTAs/SM. EPI: 0=none, 1=+bias, 2=+bias+GELU. TB: B is [N,K] (A@B^T).
// CSKIP: skip tiles above diagonal. CK: clamp K to (by+1)*128.
// All dims multiples of tile sizes; no bounds checks.
// ---------------------------------------------------------------------------
template <int EPI, bool TB, bool CSKIP, bool CK>
__global__ __launch_bounds__(256, 2)
void tf32gemm_kernel(const float* __restrict__ A, const float* __restrict__ B,
                     const float* __restrict__ bias, float* __restrict__ C,
                     int M, int N, int K, float alpha,
                     long long sA, long long sB, long long sC)
{
    constexpr int BM = 128, BN = 128, BK = 16;
    constexpr int AST = 24;                       // A smem row stride (pad, mult of 8)
    constexpr int BRM = 136;                      // B smem stride, !TB ([16][136])
    constexpr int STAGEF = 3072 + (TB ? 3072 : 2176);
    constexpr int STG = 136;                      // epilogue staging stride
    constexpr int SMEMF = (2 * STAGEF > 64 * STG) ? 2 * STAGEF : 64 * STG;

    const int bx = blockIdx.x, by = blockIdx.y, bz = blockIdx.z;
    if (CSKIP && bx > by) return;

    A += (long long)bz * sA;
    B += (long long)bz * sB;
    C += (long long)bz * sC;

    const int m0 = by * BM, n0 = bx * BN;
    const int kEnd = CK ? min(K, (by + 1) * BM) : K;
    const int nIter = kEnd / BK;

    __shared__ __align__(16) float smem[SMEMF];

    const int tid = threadIdx.x;
    const int wid = tid >> 5;
    const int wy = wid >> 2;                      // 0..1 -> M (64 rows)
    const int wx = wid & 3;                       // 0..3 -> N (32 cols)

    // ---- precompute per-thread load addresses (2 float4 per tile each) ----
    const int f0 = tid, f1 = tid + 256;
    // A: [128 rows][16 floats] -> 512 float4
    const int ar0 = f0 >> 2, ac0 = (f0 & 3) * 4;
    const int ar1 = f1 >> 2, ac1 = (f1 & 3) * 4;
    const float* aG0 = A + (long long)(m0 + ar0) * K + ac0;
    const float* aG1 = A + (long long)(m0 + ar1) * K + ac1;
    uint32_t aS0[2], aS1[2], bS0[2], bS1[2];
    const float *bG0, *bG1;
    long long bStep;                              // B ptr advance per BK
    if (!TB) {  // B [K,N]: tile [16 rows][128], smem [16][136]
        const int br0 = f0 >> 5, bc0 = (f0 & 31) * 4;
        const int br1 = f1 >> 5, bc1 = (f1 & 31) * 4;
        bG0 = B + (long long)br0 * N + n0 + bc0;
        bG1 = B + (long long)br1 * N + n0 + bc1;
        bStep = (long long)BK * N;
        #pragma unroll
        for (int s = 0; s < 2; s++) {
            bS0[s] = smem_u32(smem + s * STAGEF + 3072 + br0 * BRM + bc0);
            bS1[s] = smem_u32(smem + s * STAGEF + 3072 + br1 * BRM + bc1);
        }
    } else {    // B [N,K]: tile [128 rows][16], smem [128][24]
        const int br0 = ar0, bc0 = ac0, br1 = ar1, bc1 = ac1;
        bG0 = B + (long long)(n0 + br0) * K + bc0;
        bG1 = B + (long long)(n0 + br1) * K + bc1;
        bStep = BK;
        #pragma unroll
        for (int s = 0; s < 2; s++) {
            bS0[s] = smem_u32(smem + s * STAGEF + 3072 + br0 * AST + bc0);
            bS1[s] = smem_u32(smem + s * STAGEF + 3072 + br1 * AST + bc1);
        }
    }
    #pragma unroll
    for (int s = 0; s < 2; s++) {
        aS0[s] = smem_u32(smem + s * STAGEF + ar0 * AST + ac0);
        aS1[s] = smem_u32(smem + s * STAGEF + ar1 * AST + ac1);
    }

    wmma::fragment<wmma::accumulator, 16, 16, 8, float> c_frag[4][2];
    #pragma unroll
    for (int i = 0; i < 4; i++)
        #pragma unroll
        for (int j = 0; j < 2; j++)
            wmma::fill_fragment(c_frag[i][j], 0.0f);

    // ---- prologue: stage 0 ----
    CP_ASYNC16(aS0[0], aG0); CP_ASYNC16(aS1[0], aG1);
    CP_ASYNC16(bS0[0], bG0); CP_ASYNC16(bS1[0], bG1);
    CP_COMMIT();

    for (int it = 0; it < nIter; it++) {
        CP_WAIT0();
        __syncthreads();
        if (it + 1 < nIter) {
            const int s = (it + 1) & 1;
            const long long ka = (long long)(it + 1) * BK;
            CP_ASYNC16(aS0[s], aG0 + ka);            CP_ASYNC16(aS1[s], aG1 + ka);
            CP_ASYNC16(bS0[s], bG0 + (it + 1) * bStep); CP_ASYNC16(bS1[s], bG1 + (it + 1) * bStep);
            CP_COMMIT();
        }
        const float* As = smem + (it & 1) * STAGEF;
        const float* Bs = As + 3072;

        #pragma unroll
        for (int kk = 0; kk < BK; kk += 8) {
            wmma::fragment<wmma::matrix_a, 16, 16, 8, wmma::precision::tf32, wmma::row_major> a_frag[4];
            #pragma unroll
            for (int i = 0; i < 4; i++) {
                wmma::load_matrix_sync(a_frag[i], &As[(wy * 64 + i * 16) * AST + kk], AST);
                #pragma unroll
                for (int e = 0; e < a_frag[i].num_elements; e++)
                    a_frag[i].x[e] = wmma::__float_to_tf32(a_frag[i].x[e]);
            }
            if (!TB) {
                wmma::fragment<wmma::matrix_b, 16, 16, 8, wmma::precision::tf32, wmma::row_major> b_frag[2];
                #pragma unroll
                for (int j = 0; j < 2; j++) {
                    wmma::load_matrix_sync(b_frag[j], &Bs[kk * BRM + wx * 32 + j * 16], BRM);
                    #pragma unroll
                    for (int e = 0; e < b_frag[j].num_elements; e++)
                        b_frag[j].x[e] = wmma::__float_to_tf32(b_frag[j].x[e]);
                }
                #pragma unroll
                for (int i = 0; i < 4; i++)
                    #pragma unroll
                    for (int j = 0; j < 2; j++)
                        wmma::mma_sync(c_frag[i][j], a_frag[i], b_frag[j], c_frag[i][j]);
            } else {
                wmma::fragment<wmma::matrix_b, 16, 16, 8, wmma::precision::tf32, wmma::col_major> b_frag[2];
                #pragma unroll
                for (int j = 0; j < 2; j++) {
                    wmma::load_matrix_sync(b_frag[j], &Bs[(wx * 32 + j * 16) * AST + kk], AST);
                    #pragma unroll
                    for (int e = 0; e < b_frag[j].num_elements; e++)
                        b_frag[j].x[e] = wmma::__float_to_tf32(b_frag[j].x[e]);
                }
                #pragma unroll
                for (int i = 0; i < 4; i++)
                    #pragma unroll
                    for (int j = 0; j < 2; j++)
                        wmma::mma_sync(c_frag[i][j], a_frag[i], b_frag[j], c_frag[i][j]);
            }
        }
        __syncthreads();
    }

    // ---- epilogue: two phases through 64x128 smem staging ----
    float* Stage = smem;
    #pragma unroll
    for (int p = 0; p < 2; p++) {
        if (wy == p) {
            #pragma unroll
            for (int i = 0; i < 4; i++)
                #pragma unroll
                for (int j = 0; j < 2; j++)
                    wmma::store_matrix_sync(&Stage[(i * 16) * STG + wx * 32 + j * 16],
                                            c_frag[i][j], STG, wmma::mem_row_major);
        }
        __syncthreads();
        #pragma unroll
        for (int i = 0; i < 8; i++) {
            int f = tid + i * 256;                // 2048 float4 over 64x128
            int r = f >> 5, c4 = f & 31;
            float4 v = *(const float4*)&Stage[r * STG + c4 * 4];
            float out[4] = {v.x, v.y, v.z, v.w};
            #pragma unroll
            for (int e = 0; e < 4; e++) {
                float x = out[e] * alpha;
                if (EPI >= 1) x += bias[n0 + c4 * 4 + e];
                if (EPI == 2) x = 0.5f * x * (1.0f + erff(x * 0.70710678118654752f));
                out[e] = x;
            }
            *(float4*)(C + (long long)(m0 + p * 64 + r) * N + n0 + c4 * 4) = *(const float4*)out;
        }
        __syncthreads();
    }
}

// ---------------------------------------------------------------------------
// Causal softmax over one row t of S[b]: softmax(row[0..t]), zero row[t+1..T)
// ---------------------------------------------------------------------------
__global__ __launch_bounds__(256)
void softmax_causal_kernel(float* __restrict__ S)
{
    const int t = blockIdx.x, b = blockIdx.y;
    float* row = S + ((long long)b * TSEQ + t) * TSEQ;
    const int len = t + 1;
    const int tid = threadIdx.x;
    __shared__ float red[256];

    float m = -1e30f;
    for (int s = tid; s < len; s += 256) m = fmaxf(m, row[s]);
    red[tid] = m; __syncthreads();
    for (int o = 128; o > 0; o >>= 1) {
        if (tid < o) red[tid] = fmaxf(red[tid], red[tid + o]);
        __syncthreads();
    }
    m = red[0];
    __syncthreads();

    float sum = 0.0f;
    for (int s = tid; s < len; s += 256) {
        float e = expf(row[s] - m);
        row[s] = e;
        sum += e;
    }
    red[tid] = sum; __syncthreads();
    for (int o = 128; o > 0; o >>= 1) {
        if (tid < o) red[tid] += red[tid + o];
        __syncthreads();
    }
    const float inv = 1.0f / red[0];

    for (int s = tid; s < len; s += 256)        row[s] *= inv;
    for (int s = len + tid; s < TSEQ; s += 256) row[s] = 0.0f;
}

// ---------------------------------------------------------------------------
// out = LayerNorm(Xa + Xb) * g + be   (one block per row, D = 1024)
// ---------------------------------------------------------------------------
__global__ __launch_bounds__(256)
void add_ln_kernel(const float* __restrict__ Xa, const float* __restrict__ Xb,
                   const float* __restrict__ g,  const float* __restrict__ be,
                   float* __restrict__ out)
{
    const int row = blockIdx.x;
    const int tid = threadIdx.x;
    const float* pa = Xa + (long long)row * DMODEL;
    const float* pb = Xb + (long long)row * DMODEL;

    float x[4];
    float s1 = 0.0f, s2 = 0.0f;
    #pragma unroll
    for (int i = 0; i < 4; i++) {
        int c = tid + i * 256;
        x[i] = pa[c] + pb[c];
        s1 += x[i];
        s2 += x[i] * x[i];
    }
    __shared__ float r1[256], r2[256];
    r1[tid] = s1; r2[tid] = s2; __syncthreads();
    for (int o = 128; o > 0; o >>= 1) {
        if (tid < o) { r1[tid] += r1[tid + o]; r2[tid] += r2[tid + o]; }
        __syncthreads();
    }
    const float mu  = r1[0] * (1.0f / DMODEL);
    const float var = r2[0] * (1.0f / DMODEL) - mu * mu;
    const float inv = rsqrtf(var + 1e-5f);

    float* po = out + (long long)row * DMODEL;
    #pragma unroll
    for (int i = 0; i < 4; i++) {
        int c = tid + i * 256;
        po[c] = (x[i] - mu) * inv * g[c] + be[c];
    }
}

// ---------------------------------------------------------------------------
// Host launch
// ---------------------------------------------------------------------------
extern "C" void kernel_launch(void* const* d_in, const int* in_sizes, int n_in,
                              void* d_out, int out_size)
{
    (void)in_sizes; (void)n_in; (void)out_size;
    const float* X   = (const float*)d_in[0];
    const float* WQ  = (const float*)d_in[1];
    const float* bQ  = (const float*)d_in[2];
    const float* WK  = (const float*)d_in[3];
    const float* bK  = (const float*)d_in[4];
    const float* WV  = (const float*)d_in[5];
    const float* bV  = (const float*)d_in[6];
    const float* WO  = (const float*)d_in[7];
    const float* bO  = (const float*)d_in[8];
    const float* W1  = (const float*)d_in[9];
    const float* b1  = (const float*)d_in[10];
    const float* W2  = (const float*)d_in[11];
    const float* b2  = (const float*)d_in[12];
    const float* g1  = (const float*)d_in[13];
    const float* be1 = (const float*)d_in[14];
    const float* g2  = (const float*)d_in[15];
    const float* be2 = (const float*)d_in[16];
    float* out = (float*)d_out;

    float *Q, *Km, *Vm, *S, *H1, *FF;
    cudaGetSymbolAddress((void**)&Q,  g_Q);
    cudaGetSymbolAddress((void**)&Km, g_Km);
    cudaGetSymbolAddress((void**)&Vm, g_Vm);
    cudaGetSymbolAddress((void**)&S,  g_S);
    cudaGetSymbolAddress((void**)&H1, g_H1);
    cudaGetSymbolAddress((void**)&FF, g_FF);

    const dim3 blk(256);
    const dim3 gProj(DMODEL / 128, NTOK / 128);            // 8 x 64
    const dim3 gS(TSEQ / 128, TSEQ / 128, NB);             // 16 x 16 x 4
    const dim3 gAV(DMODEL / 128, TSEQ / 128, NB);          // 8 x 16 x 4
    const dim3 gFF1(DFF / 128, NTOK / 128);                // 32 x 64

    const long long sQK = (long long)TSEQ * DMODEL;
    const long long sSS = (long long)TSEQ * TSEQ;

    // Q, K, V projections
    tf32gemm_kernel<1, false, false, false><<<gProj, blk>>>(X, WQ, bQ, Q,  NTOK, DMODEL, DMODEL, 1.0f, 0, 0, 0);
    tf32gemm_kernel<1, false, false, false><<<gProj, blk>>>(X, WK, bK, Km, NTOK, DMODEL, DMODEL, 1.0f, 0, 0, 0);
    tf32gemm_kernel<1, false, false, false><<<gProj, blk>>>(X, WV, bV, Vm, NTOK, DMODEL, DMODEL, 1.0f, 0, 0, 0);

    // scores = (Q @ K^T) / sqrt(D)
    tf32gemm_kernel<0, true, true, false><<<gS, blk>>>(Q, Km, nullptr, S, TSEQ, TSEQ, DMODEL,
                                                       0.03125f, sQK, sQK, sSS);

    // causal softmax
    softmax_causal_kernel<<<dim3(TSEQ, NB), blk>>>(S);

    // attn = probs @ V  (reuses g_Q)
    tf32gemm_kernel<0, false, false, true><<<gAV, blk>>>(S, Vm, nullptr, Q, TSEQ, DMODEL, TSEQ,
                                                         1.0f, sSS, sQK, sQK);

    // O projection (reuses g_Km)
    tf32gemm_kernel<1, false, false, false><<<gProj, blk>>>(Q, WO, bO, Km, NTOK, DMODEL, DMODEL, 1.0f, 0, 0, 0);

    // H1 = LN(O + X)
    add_ln_kernel<<<NTOK, blk>>>(Km, X, g1, be1, H1);

    // FF = gelu(H1 @ W1 + b1)
    tf32gemm_kernel<2, false, false, false><<<gFF1, blk>>>(H1, W1, b1, FF, NTOK, DFF, DMODEL, 1.0f, 0, 0, 0);

    // H2 = FF @ W2 + b2  (reuses g_Vm)
    tf32gemm_kernel<1, false, false, false><<<gProj, blk>>>(FF, W2, b2, Vm, NTOK, DMODEL, DFF, 1.0f, 0, 0, 0);

    // out = LN(H2 + H1)
    add_ln_kernel<<<NTOK, blk>>>(Vm, H1, g2, be2, out);
}

// round 6
// speedup vs baseline: 4.4274x; 3.0417x over previous
#include <cuda_runtime.h>
#include <cuda_bf16.h>
#include <mma.h>
#include <math.h>
#include <stdint.h>

using namespace nvcuda;

// Problem constants
#define NB     4
#define TSEQ   2048
#define DMODEL 1024
#define DFF    4096
#define NTOK   (NB * TSEQ)   // 8192

typedef __nv_bfloat16 bf16;

// ---------------------------------------------------------------------------
// Scratch (device globals — no allocations allowed)
// ---------------------------------------------------------------------------
__device__ bf16  g_Xb [NTOK * DMODEL];
__device__ bf16  g_WQb[DMODEL * DMODEL];
__device__ bf16  g_WKb[DMODEL * DMODEL];
__device__ bf16  g_WVb[DMODEL * DMODEL];
__device__ bf16  g_WOb[DMODEL * DMODEL];
__device__ bf16  g_W1b[DMODEL * DFF];
__device__ bf16  g_W2b[DFF * DMODEL];
__device__ bf16  g_Qb [NTOK * DMODEL];
__device__ bf16  g_Kb [NTOK * DMODEL];
__device__ bf16  g_Vb [NTOK * DMODEL];
__device__ bf16  g_Pb [(size_t)NB * TSEQ * TSEQ];   // bf16 probs
__device__ bf16  g_AOb[NTOK * DMODEL];              // attn out bf16
__device__ bf16  g_H1b[NTOK * DMODEL];
__device__ bf16  g_FFb[(size_t)NTOK * DFF];
__device__ float g_S  [(size_t)NB * TSEQ * TSEQ];   // fp32 logits
__device__ float g_O  [NTOK * DMODEL];              // O-proj out fp32
__device__ float g_H1 [NTOK * DMODEL];
__device__ float g_H2 [NTOK * DMODEL];

// ---------------------------------------------------------------------------
// cp.async helpers
// ---------------------------------------------------------------------------
__device__ __forceinline__ uint32_t smem_u32(const void* p) {
    return (uint32_t)__cvta_generic_to_shared(p);
}
#define CP_ASYNC16(dst, src) \
    asm volatile("cp.async.cg.shared.global [%0], [%1], 16;" :: "r"(dst), "l"(src))
#define CP_COMMIT() asm volatile("cp.async.commit_group;")
#define CP_WAIT0()  asm volatile("cp.async.wait_group 0;")

// ---------------------------------------------------------------------------
// fp32 -> bf16 conversion (4 elems/thread)
// ---------------------------------------------------------------------------
__global__ __launch_bounds__(256)
void f2bf_kernel(const float* __restrict__ in, bf16* __restrict__ out, int n)
{
    int i = (blockIdx.x * 256 + threadIdx.x) * 4;
    if (i >= n) return;
    float4 v = *(const float4*)(in + i);
    ushort4 o;
    o.x = __bfloat16_as_ushort(__float2bfloat16_rn(v.x));
    o.y = __bfloat16_as_ushort(__float2bfloat16_rn(v.y));
    o.z = __bfloat16_as_ushort(__float2bfloat16_rn(v.z));
    o.w = __bfloat16_as_ushort(__float2bfloat16_rn(v.w));
    *(ushort4*)(out + i) = o;
}

// ---------------------------------------------------------------------------
// bf16 tensor-core GEMM, cp.async double-buffered, fp32 accumulate.
// Block tile 128x128, BK=32, 256 threads (8 warps, 64x32 warp tiles).
//   EPI: 0=none, 1=+bias, 2=+bias+GELU
//   OUTB: write bf16 (else fp32)
//   TB  : B is [N,K] row-major (A@B^T)
//   CSKIP: skip tiles above diagonal; CK: clamp K to (by+1)*128
// ---------------------------------------------------------------------------
template <int EPI, bool OUTB, bool TB, bool CSKIP, bool CK>
__global__ __launch_bounds__(256, 2)
void bfgemm_kernel(const bf16* __restrict__ A, const bf16* __restrict__ B,
                   const float* __restrict__ bias, void* __restrict__ Cv,
                   int M, int N, int K, float alpha,
                   long long sA, long long sB, long long sC)
{
    constexpr int BM = 128, BN = 128, BK = 32;
    constexpr int AST = 40;                        // A/B(TB) smem stride (bf16 elems)
    constexpr int BST = 136;                       // B(!TB) smem stride
    constexpr int A_ELE = 128 * AST;               // 5120
    constexpr int B_ELE = TB ? 128 * AST : 32 * BST;
    constexpr int STAGE = A_ELE + B_ELE;           // bf16 elems per stage
    constexpr int STG = 136;                       // fp32 epilogue staging stride
    constexpr int SMEM_BYTES = (2 * STAGE * 2 > 64 * STG * 4) ? 2 * STAGE * 2 : 64 * STG * 4;

    const int bx = blockIdx.x, by = blockIdx.y, bz = blockIdx.z;
    if (CSKIP && bx > by) return;

    A += (long long)bz * sA;
    B += (long long)bz * sB;

    const int m0 = by * BM, n0 = bx * BN;
    const int kEnd = CK ? min(K, (by + 1) * BM) : K;
    const int nIter = kEnd / BK;

    __shared__ __align__(16) char smem_raw[SMEM_BYTES];
    bf16* smem = (bf16*)smem_raw;

    const int tid = threadIdx.x;
    const int wid = tid >> 5;
    const int wy = wid >> 2;                       // 0..1 -> M (64 rows)
    const int wx = wid & 3;                        // 0..3 -> N (32 cols)

    // ---- per-thread cp.async addresses ----
    const int f0 = tid, f1 = tid + 256;
    const int ar0 = f0 >> 2, ac0 = (f0 & 3) * 8;
    const int ar1 = f1 >> 2, ac1 = (f1 & 3) * 8;
    const bf16* aG0 = A + (long long)(m0 + ar0) * K + ac0;
    const bf16* aG1 = A + (long long)(m0 + ar1) * K + ac1;
    uint32_t aS0[2], aS1[2], bS0[2], bS1[2];
    const bf16 *bG0, *bG1;
    long long bStep;
    if (!TB) {  // B [K,N]: tile [32][128] -> smem [32][136]
        const int br0 = f0 >> 4, bc0 = (f0 & 15) * 8;
        const int br1 = f1 >> 4, bc1 = (f1 & 15) * 8;
        bG0 = B + (long long)br0 * N + n0 + bc0;
        bG1 = B + (long long)br1 * N + n0 + bc1;
        bStep = (long long)BK * N;
        #pragma unroll
        for (int s = 0; s < 2; s++) {
            bS0[s] = smem_u32(smem + s * STAGE + A_ELE + br0 * BST + bc0);
            bS1[s] = smem_u32(smem + s * STAGE + A_ELE + br1 * BST + bc1);
        }
    } else {    // B [N,K]: tile [128][32] -> smem [128][40]
        bG0 = B + (long long)(n0 + ar0) * K + ac0;
        bG1 = B + (long long)(n0 + ar1) * K + ac1;
        bStep = BK;
        #pragma unroll
        for (int s = 0; s < 2; s++) {
            bS0[s] = smem_u32(smem + s * STAGE + A_ELE + ar0 * AST + ac0);
            bS1[s] = smem_u32(smem + s * STAGE + A_ELE + ar1 * AST + ac1);
        }
    }
    #pragma unroll
    for (int s = 0; s < 2; s++) {
        aS0[s] = smem_u32(smem + s * STAGE + ar0 * AST + ac0);
        aS1[s] = smem_u32(smem + s * STAGE + ar1 * AST + ac1);
    }

    wmma::fragment<wmma::accumulator, 16, 16, 16, float> c_frag[4][2];
    #pragma unroll
    for (int i = 0; i < 4; i++)
        #pragma unroll
        for (int j = 0; j < 2; j++)
            wmma::fill_fragment(c_frag[i][j], 0.0f);

    // ---- prologue ----
    CP_ASYNC16(aS0[0], aG0); CP_ASYNC16(aS1[0], aG1);
    CP_ASYNC16(bS0[0], bG0); CP_ASYNC16(bS1[0], bG1);
    CP_COMMIT();

    for (int it = 0; it < nIter; it++) {
        CP_WAIT0();
        __syncthreads();
        if (it + 1 < nIter) {
            const int s = (it + 1) & 1;
            const long long ka = (long long)(it + 1) * BK;
            CP_ASYNC16(aS0[s], aG0 + ka);               CP_ASYNC16(aS1[s], aG1 + ka);
            CP_ASYNC16(bS0[s], bG0 + (it + 1) * bStep); CP_ASYNC16(bS1[s], bG1 + (it + 1) * bStep);
            CP_COMMIT();
        }
        const bf16* As = smem + (it & 1) * STAGE;
        const bf16* Bs = As + A_ELE;

        #pragma unroll
        for (int kk = 0; kk < BK; kk += 16) {
            wmma::fragment<wmma::matrix_a, 16, 16, 16, bf16, wmma::row_major> a_frag[4];
            #pragma unroll
            for (int i = 0; i < 4; i++)
                wmma::load_matrix_sync(a_frag[i], &As[(wy * 64 + i * 16) * AST + kk], AST);
            if (!TB) {
                wmma::fragment<wmma::matrix_b, 16, 16, 16, bf16, wmma::row_major> b_frag[2];
                #pragma unroll
                for (int j = 0; j < 2; j++)
                    wmma::load_matrix_sync(b_frag[j], &Bs[kk * BST + wx * 32 + j * 16], BST);
                #pragma unroll
                for (int i = 0; i < 4; i++)
                    #pragma unroll
                    for (int j = 0; j < 2; j++)
                        wmma::mma_sync(c_frag[i][j], a_frag[i], b_frag[j], c_frag[i][j]);
            } else {
                wmma::fragment<wmma::matrix_b, 16, 16, 16, bf16, wmma::col_major> b_frag[2];
                #pragma unroll
                for (int j = 0; j < 2; j++)
                    wmma::load_matrix_sync(b_frag[j], &Bs[(wx * 32 + j * 16) * AST + kk], AST);
                #pragma unroll
                for (int i = 0; i < 4; i++)
                    #pragma unroll
                    for (int j = 0; j < 2; j++)
                        wmma::mma_sync(c_frag[i][j], a_frag[i], b_frag[j], c_frag[i][j]);
            }
        }
        __syncthreads();
    }

    // ---- epilogue: two phases through 64x128 fp32 smem staging ----
    float* Stage = (float*)smem_raw;
    #pragma unroll
    for (int p = 0; p < 2; p++) {
        if (wy == p) {
            #pragma unroll
            for (int i = 0; i < 4; i++)
                #pragma unroll
                for (int j = 0; j < 2; j++)
                    wmma::store_matrix_sync(&Stage[(i * 16) * STG + wx * 32 + j * 16],
                                            c_frag[i][j], STG, wmma::mem_row_major);
        }
        __syncthreads();
        #pragma unroll
        for (int i = 0; i < 8; i++) {
            int f = tid + i * 256;                 // 2048 float4 over 64x128
            int r = f >> 5, c4 = f & 31;
            float4 v = *(const float4*)&Stage[r * STG + c4 * 4];
            float o[4] = {v.x, v.y, v.z, v.w};
            #pragma unroll
            for (int e = 0; e < 4; e++) {
                float x = o[e] * alpha;
                if (EPI >= 1) x += bias[n0 + c4 * 4 + e];
                if (EPI == 2) x = 0.5f * x * (1.0f + erff(x * 0.70710678118654752f));
                o[e] = x;
            }
            const long long off = (long long)bz * sC + (long long)(m0 + p * 64 + r) * N + n0 + c4 * 4;
            if (OUTB) {
                ushort4 u;
                u.x = __bfloat16_as_ushort(__float2bfloat16_rn(o[0]));
                u.y = __bfloat16_as_ushort(__float2bfloat16_rn(o[1]));
                u.z = __bfloat16_as_ushort(__float2bfloat16_rn(o[2]));
                u.w = __bfloat16_as_ushort(__float2bfloat16_rn(o[3]));
                *(ushort4*)((bf16*)Cv + off) = u;
            } else {
                *(float4*)((float*)Cv + off) = *(const float4*)o;
            }
        }
        __syncthreads();
    }
}

// ---------------------------------------------------------------------------
// Causal softmax: fp32 logits row -> bf16 probs row (zero tail)
// ---------------------------------------------------------------------------
__global__ __launch_bounds__(256)
void softmax_causal_kernel(const float* __restrict__ S, bf16* __restrict__ P)
{
    const int t = blockIdx.x, b = blockIdx.y;
    const float* row = S + ((long long)b * TSEQ + t) * TSEQ;
    bf16* prow = P + ((long long)b * TSEQ + t) * TSEQ;
    const int len = t + 1;
    const int tid = threadIdx.x;
    __shared__ float red[256];

    float m = -1e30f;
    for (int s = tid; s < len; s += 256) m = fmaxf(m, row[s]);
    red[tid] = m; __syncthreads();
    for (int o = 128; o > 0; o >>= 1) {
        if (tid < o) red[tid] = fmaxf(red[tid], red[tid + o]);
        __syncthreads();
    }
    m = red[0];
    __syncthreads();

    float sum = 0.0f;
    for (int s = tid; s < len; s += 256) sum += expf(row[s] - m);
    red[tid] = sum; __syncthreads();
    for (int o = 128; o > 0; o >>= 1) {
        if (tid < o) red[tid] += red[tid + o];
        __syncthreads();
    }
    const float inv = 1.0f / red[0];

    for (int s = tid; s < len; s += 256)
        prow[s] = __float2bfloat16_rn(expf(row[s] - m) * inv);
    for (int s = len + tid; s < TSEQ; s += 256)
        prow[s] = __float2bfloat16_rn(0.0f);
}

// ---------------------------------------------------------------------------
// out = LayerNorm(Xa + Xb) * g + be ; optional bf16 copy
// ---------------------------------------------------------------------------
__global__ __launch_bounds__(256)
void add_ln_kernel(const float* __restrict__ Xa, const float* __restrict__ Xb,
                   const float* __restrict__ g,  const float* __restrict__ be,
                   float* __restrict__ out, bf16* __restrict__ out_bf)
{
    const int row = blockIdx.x;
    const int tid = threadIdx.x;
    const float* pa = Xa + (long long)row * DMODEL;
    const float* pb = Xb + (long long)row * DMODEL;

    float x[4];
    float s1 = 0.0f, s2 = 0.0f;
    #pragma unroll
    for (int i = 0; i < 4; i++) {
        int c = tid + i * 256;
        x[i] = pa[c] + pb[c];
        s1 += x[i];
        s2 += x[i] * x[i];
    }
    __shared__ float r1[256], r2[256];
    r1[tid] = s1; r2[tid] = s2; __syncthreads();
    for (int o = 128; o > 0; o >>= 1) {
        if (tid < o) { r1[tid] += r1[tid + o]; r2[tid] += r2[tid + o]; }
        __syncthreads();
    }
    const float mu  = r1[0] * (1.0f / DMODEL);
    const float var = r2[0] * (1.0f / DMODEL) - mu * mu;
    const float inv = rsqrtf(var + 1e-5f);

    float* po = out + (long long)row * DMODEL;
    #pragma unroll
    for (int i = 0; i < 4; i++) {
        int c = tid + i * 256;
        float v = (x[i] - mu) * inv * g[c] + be[c];
        po[c] = v;
        if (out_bf) out_bf[(long long)row * DMODEL + c] = __float2bfloat16_rn(v);
    }
}

// ---------------------------------------------------------------------------
// Host launch
// ---------------------------------------------------------------------------
extern "C" void kernel_launch(void* const* d_in, const int* in_sizes, int n_in,
                              void* d_out, int out_size)
{
    (void)in_sizes; (void)n_in; (void)out_size;
    const float* X   = (const float*)d_in[0];
    const float* WQ  = (const float*)d_in[1];
    const float* bQ  = (const float*)d_in[2];
    const float* WK  = (const float*)d_in[3];
    const float* bK  = (const float*)d_in[4];
    const float* WV  = (const float*)d_in[5];
    const float* bV  = (const float*)d_in[6];
    const float* WO  = (const float*)d_in[7];
    const float* bO  = (const float*)d_in[8];
    const float* W1  = (const float*)d_in[9];
    const float* b1  = (const float*)d_in[10];
    const float* W2  = (const float*)d_in[11];
    const float* b2  = (const float*)d_in[12];
    const float* g1  = (const float*)d_in[13];
    const float* be1 = (const float*)d_in[14];
    const float* g2  = (const float*)d_in[15];
    const float* be2 = (const float*)d_in[16];
    float* out = (float*)d_out;

    bf16 *Xb, *WQb, *WKb, *WVb, *WOb, *W1b, *W2b, *Qb, *Kb, *Vb, *Pb, *AOb, *H1b, *FFb;
    float *S, *O, *H1, *H2;
    cudaGetSymbolAddress((void**)&Xb,  g_Xb);
    cudaGetSymbolAddress((void**)&WQb, g_WQb);
    cudaGetSymbolAddress((void**)&WKb, g_WKb);
    cudaGetSymbolAddress((void**)&WVb, g_WVb);
    cudaGetSymbolAddress((void**)&WOb, g_WOb);
    cudaGetSymbolAddress((void**)&W1b, g_W1b);
    cudaGetSymbolAddress((void**)&W2b, g_W2b);
    cudaGetSymbolAddress((void**)&Qb,  g_Qb);
    cudaGetSymbolAddress((void**)&Kb,  g_Kb);
    cudaGetSymbolAddress((void**)&Vb,  g_Vb);
    cudaGetSymbolAddress((void**)&Pb,  g_Pb);
    cudaGetSymbolAddress((void**)&AOb, g_AOb);
    cudaGetSymbolAddress((void**)&H1b, g_H1b);
    cudaGetSymbolAddress((void**)&FFb, g_FFb);
    cudaGetSymbolAddress((void**)&S,   g_S);
    cudaGetSymbolAddress((void**)&O,   g_O);
    cudaGetSymbolAddress((void**)&H1,  g_H1);
    cudaGetSymbolAddress((void**)&H2,  g_H2);

    const dim3 blk(256);

    // ---- convert inputs to bf16 ----
    f2bf_kernel<<<NTOK * DMODEL / 1024, blk>>>(X,  Xb,  NTOK * DMODEL);
    f2bf_kernel<<<DMODEL * DMODEL / 1024, blk>>>(WQ, WQb, DMODEL * DMODEL);
    f2bf_kernel<<<DMODEL * DMODEL / 1024, blk>>>(WK, WKb, DMODEL * DMODEL);
    f2bf_kernel<<<DMODEL * DMODEL / 1024, blk>>>(WV, WVb, DMODEL * DMODEL);
    f2bf_kernel<<<DMODEL * DMODEL / 1024, blk>>>(WO, WOb, DMODEL * DMODEL);
    f2bf_kernel<<<DMODEL * DFF / 1024, blk>>>(W1, W1b, DMODEL * DFF);
    f2bf_kernel<<<DFF * DMODEL / 1024, blk>>>(W2, W2b, DFF * DMODEL);

    const dim3 gProj(DMODEL / 128, NTOK / 128);            // 8 x 64
    const dim3 gS(TSEQ / 128, TSEQ / 128, NB);             // 16 x 16 x 4
    const dim3 gAV(DMODEL / 128, TSEQ / 128, NB);          // 8 x 16 x 4
    const dim3 gFF1(DFF / 128, NTOK / 128);                // 32 x 64

    const long long sQK = (long long)TSEQ * DMODEL;
    const long long sSS = (long long)TSEQ * TSEQ;

    // Q, K, V projections -> bf16
    bfgemm_kernel<1, true, false, false, false><<<gProj, blk>>>(Xb, WQb, bQ, Qb, NTOK, DMODEL, DMODEL, 1.0f, 0, 0, 0);
    bfgemm_kernel<1, true, false, false, false><<<gProj, blk>>>(Xb, WKb, bK, Kb, NTOK, DMODEL, DMODEL, 1.0f, 0, 0, 0);
    bfgemm_kernel<1, true, false, false, false><<<gProj, blk>>>(Xb, WVb, bV, Vb, NTOK, DMODEL, DMODEL, 1.0f, 0, 0, 0);

    // scores = (Q @ K^T)/sqrt(D) -> fp32 S
    bfgemm_kernel<0, false, true, true, false><<<gS, blk>>>(Qb, Kb, nullptr, S, TSEQ, TSEQ, DMODEL,
                                                            0.03125f, sQK, sQK, sSS);

    // causal softmax fp32 -> bf16 probs
    softmax_causal_kernel<<<dim3(TSEQ, NB), blk>>>(S, Pb);

    // attn = probs @ V -> bf16
    bfgemm_kernel<0, true, false, false, true><<<gAV, blk>>>(Pb, Vb, nullptr, AOb, TSEQ, DMODEL, TSEQ,
                                                             1.0f, sSS, sQK, sQK);

    // O projection -> fp32
    bfgemm_kernel<1, false, false, false, false><<<gProj, blk>>>(AOb, WOb, bO, O, NTOK, DMODEL, DMODEL, 1.0f, 0, 0, 0);

    // H1 = LN(O + X) -> fp32 + bf16
    add_ln_kernel<<<NTOK, blk>>>(O, X, g1, be1, H1, H1b);

    // FF = gelu(H1 @ W1 + b1) -> bf16
    bfgemm_kernel<2, true, false, false, false><<<gFF1, blk>>>(H1b, W1b, b1, FFb, NTOK, DFF, DMODEL, 1.0f, 0, 0, 0);

    // H2 = FF @ W2 + b2 -> fp32
    bfgemm_kernel<1, false, false, false, false><<<gProj, blk>>>(FFb, W2b, b2, H2, NTOK, DMODEL, DFF, 1.0f, 0, 0, 0);

    // out = LN(H2 + H1)
    add_ln_kernel<<<NTOK, blk>>>(H2, H1, g2, be2, out, nullptr);
}